// round 2
// baseline (speedup 1.0000x reference)
#include <cuda_runtime.h>
#include <math.h>

#define NPTS 400000
#define MQ   100000
#define NBR  16
#define CIN  64
#define D2   32
#define COUT 128
#define KP   15
#define INV_EXTENT 2.0f   // 1/EXTENT, EXTENT = 0.5
#define EPS 1e-5f
#define SLOPE 0.2f

#define G1GRID 592
#define G5GRID 592
#define QPB 64
#define KPGRID ((MQ + QPB - 1) / QPB)   // 1563
#define KD (KP * D2)                    // 480

// ---------------- scratch (static device globals; no runtime allocation) ----
__device__ float g_y1[(size_t)NPTS * D2];     // raw x@W_u1 (pre-BN)
__device__ float g_kp[(size_t)MQ * D2];       // kpconv output (pre-BN)
__device__ float g_sx[(size_t)MQ * CIN];      // shortcut max-pool
__device__ float g_y3[(size_t)MQ * COUT];     // h2@W_u2 (pre-BN)
__device__ float g_p1[G1GRID * 2 * D2];
__device__ float g_p2[KPGRID * 2 * D2];
__device__ float g_p3[G5GRID * 2 * COUT];
__device__ float g_a1[D2], g_c1[D2];
__device__ float g_a2[D2], g_c2[D2];
__device__ float g_a3[COUT], g_c3[COUT];

__device__ __forceinline__ float leaky(float v) { return v >= 0.f ? v : SLOPE * v; }

// ---------------- K1: y1 = x @ W_u1, accumulate per-column sum/sumsq --------
__global__ void k_gemm1(const float* __restrict__ x, const float* __restrict__ W)
{
    __shared__ float Wsm[CIN * D2];
    __shared__ float sred[8][D2], ssred[8][D2];
    int tid = threadIdx.x, lane = tid & 31, w = tid >> 5;
    for (int i = tid; i < CIN * D2; i += 256) Wsm[i] = W[i];
    __syncthreads();
    float s = 0.f, ss = 0.f;
    for (int r = blockIdx.x * 8 + w; r < NPTS; r += G1GRID * 8) {
        float x0 = x[(size_t)r * CIN + lane];
        float x1 = x[(size_t)r * CIN + 32 + lane];
        float acc = 0.f;
        #pragma unroll
        for (int i = 0; i < 32; i++)
            acc = fmaf(__shfl_sync(0xffffffffu, x0, i), Wsm[i * D2 + lane], acc);
        #pragma unroll
        for (int i = 0; i < 32; i++)
            acc = fmaf(__shfl_sync(0xffffffffu, x1, i), Wsm[(i + 32) * D2 + lane], acc);
        g_y1[(size_t)r * D2 + lane] = acc;
        s += acc; ss += acc * acc;
    }
    sred[w][lane] = s; ssred[w][lane] = ss;
    __syncthreads();
    if (tid < D2) {
        float S = 0.f, SS = 0.f;
        #pragma unroll
        for (int j = 0; j < 8; j++) { S += sred[j][tid]; SS += ssred[j][tid]; }
        g_p1[blockIdx.x * 2 * D2 + tid] = S;
        g_p1[blockIdx.x * 2 * D2 + D2 + tid] = SS;
    }
}

// ---------------- finalize BN stats -> folded affine (a, c) -----------------
__global__ void k_fin(int stage, const float* __restrict__ g, const float* __restrict__ b)
{
    int t = threadIdx.x;
    const float* part; int nblk; int C; float invn; float* a; float* c;
    if (stage == 1)      { part = g_p1; nblk = G1GRID; C = D2;   invn = 1.f / NPTS; a = g_a1; c = g_c1; }
    else if (stage == 2) { part = g_p2; nblk = KPGRID; C = D2;   invn = 1.f / MQ;   a = g_a2; c = g_c2; }
    else                 { part = g_p3; nblk = G5GRID; C = COUT; invn = 1.f / MQ;   a = g_a3; c = g_c3; }
    if (t >= C) return;
    float s = 0.f, ss = 0.f;
    #pragma unroll 4
    for (int i = 0; i < nblk; i++) {
        s  += part[i * 2 * C + t];
        ss += part[i * 2 * C + C + t];
    }
    float mu  = s * invn;
    float var = ss * invn - mu * mu;
    float A   = g[t] * rsqrtf(var + EPS);
    a[t] = A;
    c[t] = b[t] - mu * A;
}

// ---------------- K3: KPConv (gather + weights, then A @ Kv) ----------------
// smem: A[QPB][480] | Kv[480][32] | kx,ky,kz,k2[15] | red[2][8][32]
__global__ void k_kpconv(const float* __restrict__ pos, const float* __restrict__ qpos,
                         const int* __restrict__ idx, const float* __restrict__ Kpts,
                         const float* __restrict__ Kv)
{
    extern __shared__ float smem[];
    float* A   = smem;                 // QPB*KD = 30720
    float* Kvs = A + QPB * KD;         // 15360
    float* kx  = Kvs + KD * D2;
    float* ky  = kx + KP;
    float* kz  = ky + KP;
    float* k2  = kz + KP;
    float* red = k2 + KP;              // 512

    int tid = threadIdx.x, lane = tid & 31, w = tid >> 5;
    for (int i = tid; i < KD * D2; i += 256) Kvs[i] = Kv[i];
    if (tid < KP) {
        float a = Kpts[tid * 3], b = Kpts[tid * 3 + 1], cc = Kpts[tid * 3 + 2];
        kx[tid] = a; ky[tid] = b; kz[tid] = cc; k2[tid] = a * a + b * b + cc * cc;
    }
    __syncthreads();

    float a1 = g_a1[lane], c1 = g_c1[lane];
    int q0 = blockIdx.x * QPB;

    // ---- phase 1: warp per query (8 queries per warp) ----
    for (int j = 0; j < 8; j++) {
        int m = q0 + w * 8 + j;
        float wacc[KP];
        #pragma unroll
        for (int k = 0; k < KP; k++) wacc[k] = 0.f;
        if (m < MQ) {
            float qx = __ldg(&qpos[m * 3]), qy = __ldg(&qpos[m * 3 + 1]), qz = __ldg(&qpos[m * 3 + 2]);
            int idv = (lane < NBR) ? __ldg(&idx[m * NBR + lane]) : NPTS;
            #pragma unroll
            for (int nb = 0; nb < NBR; nb++) {
                int id = __shfl_sync(0xffffffffu, idv, nb);
                if (id < NPTS) {
                    float rx = __ldg(&pos[id * 3])     - qx;
                    float ry = __ldg(&pos[id * 3 + 1]) - qy;
                    float rz = __ldg(&pos[id * 3 + 2]) - qz;
                    float r2 = rx * rx + ry * ry + rz * rz;
                    float wk = 0.f;
                    if (lane < KP) {
                        float sq = r2 + k2[lane]
                                 - 2.f * (rx * kx[lane] + ry * ky[lane] + rz * kz[lane]);
                        float d = sqrtf(fmaxf(sq, 0.f));
                        wk = fmaxf(1.f - d * INV_EXTENT, 0.f);
                    }
                    float f = __ldg(&g_y1[(size_t)id * D2 + lane]);
                    f = leaky(fmaf(a1, f, c1));
                    #pragma unroll
                    for (int k = 0; k < KP; k++)
                        wacc[k] = fmaf(__shfl_sync(0xffffffffu, wk, k), f, wacc[k]);
                }
            }
        }
        #pragma unroll
        for (int k = 0; k < KP; k++)
            A[(w * 8 + j) * KD + k * D2 + lane] = wacc[k];
    }
    __syncthreads();

    // ---- phase 2: out[q][e] = sum_kd A[q][kd] * Kv[kd][e], 8 queries/thread ----
    int e = lane, qs = w;
    float acc[8];
    #pragma unroll
    for (int j = 0; j < 8; j++) acc[j] = 0.f;
    const float* Arow = A + qs * 8 * KD;
    for (int kd = 0; kd < KD; kd += 4) {
        float kv0 = Kvs[(kd + 0) * D2 + e];
        float kv1 = Kvs[(kd + 1) * D2 + e];
        float kv2 = Kvs[(kd + 2) * D2 + e];
        float kv3 = Kvs[(kd + 3) * D2 + e];
        #pragma unroll
        for (int j = 0; j < 8; j++) {
            float4 av = *(const float4*)(Arow + j * KD + kd);
            acc[j] = fmaf(kv0, av.x, acc[j]);
            acc[j] = fmaf(kv1, av.y, acc[j]);
            acc[j] = fmaf(kv2, av.z, acc[j]);
            acc[j] = fmaf(kv3, av.w, acc[j]);
        }
    }
    float s = 0.f, ss = 0.f;
    #pragma unroll
    for (int j = 0; j < 8; j++) {
        int m = q0 + qs * 8 + j;
        if (m < MQ) {
            g_kp[(size_t)m * D2 + e] = acc[j];
            s += acc[j]; ss += acc[j] * acc[j];
        }
    }
    red[w * D2 + e] = s;
    red[256 + w * D2 + e] = ss;
    __syncthreads();
    if (tid < D2) {
        float S = 0.f, SS = 0.f;
        #pragma unroll
        for (int j = 0; j < 8; j++) { S += red[j * D2 + tid]; SS += red[256 + j * D2 + tid]; }
        g_p2[blockIdx.x * 2 * D2 + tid] = S;
        g_p2[blockIdx.x * 2 * D2 + D2 + tid] = SS;
    }
}

// ---------------- K5: h2 = act(bn2(kp)); y3 = h2 @ W_u2; stats3 -------------
__global__ void k_gemm2(const float* __restrict__ W2)
{
    __shared__ float Wsm[D2 * COUT];
    __shared__ float red[2][8][COUT];
    int tid = threadIdx.x, lane = tid & 31, w = tid >> 5;
    for (int i = tid; i < D2 * COUT; i += 256) Wsm[i] = W2[i];
    __syncthreads();
    float a2 = g_a2[lane], c2 = g_c2[lane];
    float s[4] = {0, 0, 0, 0}, ss[4] = {0, 0, 0, 0};
    for (int m = blockIdx.x * 8 + w; m < MQ; m += G5GRID * 8) {
        float v = g_kp[(size_t)m * D2 + lane];
        float h = leaky(fmaf(a2, v, c2));
        float a0 = 0.f, b0 = 0.f, cc0 = 0.f, d0 = 0.f;
        #pragma unroll
        for (int i = 0; i < 32; i++) {
            float hv = __shfl_sync(0xffffffffu, h, i);
            a0  = fmaf(hv, Wsm[i * COUT + lane],      a0);
            b0  = fmaf(hv, Wsm[i * COUT + 32 + lane], b0);
            cc0 = fmaf(hv, Wsm[i * COUT + 64 + lane], cc0);
            d0  = fmaf(hv, Wsm[i * COUT + 96 + lane], d0);
        }
        size_t o = (size_t)m * COUT;
        g_y3[o + lane] = a0; g_y3[o + 32 + lane] = b0;
        g_y3[o + 64 + lane] = cc0; g_y3[o + 96 + lane] = d0;
        s[0] += a0;  ss[0] += a0 * a0;   s[1] += b0;  ss[1] += b0 * b0;
        s[2] += cc0; ss[2] += cc0 * cc0; s[3] += d0;  ss[3] += d0 * d0;
    }
    #pragma unroll
    for (int r = 0; r < 4; r++) {
        red[0][w][lane + 32 * r] = s[r];
        red[1][w][lane + 32 * r] = ss[r];
    }
    __syncthreads();
    if (tid < COUT) {
        float S = 0.f, SS = 0.f;
        #pragma unroll
        for (int j = 0; j < 8; j++) { S += red[0][j][tid]; SS += red[1][j][tid]; }
        g_p3[blockIdx.x * 2 * COUT + tid] = S;
        g_p3[blockIdx.x * 2 * COUT + COUT + tid] = SS;
    }
}

// ---------------- K7: shortcut max-pool gather ------------------------------
__global__ void k_sx(const float* __restrict__ x, const int* __restrict__ idx)
{
    int tid = threadIdx.x, lane = tid & 31, w = tid >> 5;
    int m = blockIdx.x * 8 + w;
    if (m >= MQ) return;
    float m0 = -INFINITY, m1 = -INFINITY;
    int idv = (lane < NBR) ? __ldg(&idx[m * NBR + lane]) : NPTS;
    #pragma unroll
    for (int nb = 0; nb < NBR; nb++) {
        int id = __shfl_sync(0xffffffffu, idv, nb);
        float v0 = 0.f, v1 = 0.f;
        if (id < NPTS) {
            v0 = __ldg(&x[(size_t)id * CIN + lane]);
            v1 = __ldg(&x[(size_t)id * CIN + 32 + lane]);
        }
        m0 = fmaxf(m0, v0);
        m1 = fmaxf(m1, v1);
    }
    g_sx[(size_t)m * CIN + lane] = m0;
    g_sx[(size_t)m * CIN + 32 + lane] = m1;
}

// ---------------- K8: out = act(bn3(y3)) + sx @ W_sc ------------------------
__global__ void k_final(const float* __restrict__ Wsc, float* __restrict__ out)
{
    __shared__ float Wsm[CIN * COUT];   // 32 KB
    int tid = threadIdx.x, lane = tid & 31, w = tid >> 5;
    for (int i = tid; i < CIN * COUT; i += 256) Wsm[i] = Wsc[i];
    __syncthreads();
    int m = blockIdx.x * 8 + w;
    if (m >= MQ) return;
    float s0 = g_sx[(size_t)m * CIN + lane];
    float s1 = g_sx[(size_t)m * CIN + 32 + lane];
    float acc0 = 0.f, acc1 = 0.f, acc2 = 0.f, acc3 = 0.f;
    #pragma unroll
    for (int i = 0; i < 32; i++) {
        float sv = __shfl_sync(0xffffffffu, s0, i);
        acc0 = fmaf(sv, Wsm[i * COUT + lane],      acc0);
        acc1 = fmaf(sv, Wsm[i * COUT + 32 + lane], acc1);
        acc2 = fmaf(sv, Wsm[i * COUT + 64 + lane], acc2);
        acc3 = fmaf(sv, Wsm[i * COUT + 96 + lane], acc3);
    }
    #pragma unroll
    for (int i = 0; i < 32; i++) {
        float sv = __shfl_sync(0xffffffffu, s1, i);
        acc0 = fmaf(sv, Wsm[(i + 32) * COUT + lane],      acc0);
        acc1 = fmaf(sv, Wsm[(i + 32) * COUT + 32 + lane], acc1);
        acc2 = fmaf(sv, Wsm[(i + 32) * COUT + 64 + lane], acc2);
        acc3 = fmaf(sv, Wsm[(i + 32) * COUT + 96 + lane], acc3);
    }
    size_t o = (size_t)m * COUT;
    float accs[4] = {acc0, acc1, acc2, acc3};
    #pragma unroll
    for (int r = 0; r < 4; r++) {
        int e = lane + 32 * r;
        float y = g_y3[o + e];
        float h = leaky(fmaf(g_a3[e], y, g_c3[e]));
        out[o + e] = h + accs[r];
    }
}

// ---------------- launch ----------------------------------------------------
extern "C" void kernel_launch(void* const* d_in, const int* in_sizes, int n_in,
                              void* d_out, int out_size)
{
    const float* x    = (const float*)d_in[0];
    const float* pos  = (const float*)d_in[1];
    const float* qpos = (const float*)d_in[2];
    const int*   idx  = (const int*)d_in[3];
    const float* Wu1  = (const float*)d_in[4];
    const float* g1   = (const float*)d_in[5];
    const float* b1   = (const float*)d_in[6];
    const float* Kpts = (const float*)d_in[7];
    const float* Kv   = (const float*)d_in[8];
    const float* gk   = (const float*)d_in[9];
    const float* bk   = (const float*)d_in[10];
    const float* Wu2  = (const float*)d_in[11];
    const float* g2   = (const float*)d_in[12];
    const float* b2   = (const float*)d_in[13];
    const float* Wsc  = (const float*)d_in[14];
    float* out = (float*)d_out;

    const int SMEM_KP = (QPB * KD + KD * D2 + 4 * KP + 512) * (int)sizeof(float); // 186608
    cudaFuncSetAttribute(k_kpconv, cudaFuncAttributeMaxDynamicSharedMemorySize, SMEM_KP);

    k_gemm1<<<G1GRID, 256>>>(x, Wu1);
    k_fin<<<1, 128>>>(1, g1, b1);
    k_kpconv<<<KPGRID, 256, SMEM_KP>>>(pos, qpos, idx, Kpts, Kv);
    k_fin<<<1, 128>>>(2, gk, bk);
    k_gemm2<<<G5GRID, 256>>>(Wu2);
    k_fin<<<1, 128>>>(3, g2, b2);
    k_sx<<<(MQ + 7) / 8, 256>>>(x, idx);
    k_final<<<(MQ + 7) / 8, 256>>>(Wsc, out);
}

// round 3
// speedup vs baseline: 1.1323x; 1.1323x over previous
#include <cuda_runtime.h>
#include <math.h>

#define NPTS 400000
#define MQ   100000
#define NBR  16
#define CIN  64
#define D2   32
#define COUT 128
#define KP   15
#define INV_EXTENT 2.0f   // 1/EXTENT, EXTENT = 0.5
#define EPS 1e-5f
#define SLOPE 0.2f

#define G1GRID 592
#define G5GRID 592
#define QPB 64
#define KPGRID ((MQ + QPB - 1) / QPB)   // 1563
#define KD (KP * D2)                    // 480

// ---------------- scratch (static device globals; no runtime allocation) ----
__device__ float g_y1[(size_t)NPTS * D2];     // raw x@W_u1 (pre-BN)
__device__ float g_kp[(size_t)MQ * D2];       // kpconv output (pre-BN)
__device__ float g_sx[(size_t)MQ * CIN];      // shortcut max-pool
__device__ float g_y3[(size_t)MQ * COUT];     // h2@W_u2 (pre-BN)
__device__ float g_p1[G1GRID * 2 * D2];
__device__ float g_p2[KPGRID * 2 * D2];
__device__ float g_p3[G5GRID * 2 * COUT];
__device__ float g_a1[D2], g_c1[D2];
__device__ float g_a2[D2], g_c2[D2];
__device__ float g_a3[COUT], g_c3[COUT];

__device__ __forceinline__ float leaky(float v) { return v >= 0.f ? v : SLOPE * v; }

// ---------------- K1: y1 = x @ W_u1, accumulate per-column sum/sumsq --------
__global__ void k_gemm1(const float* __restrict__ x, const float* __restrict__ W)
{
    __shared__ float Wsm[CIN * D2];
    __shared__ float sred[8][D2], ssred[8][D2];
    int tid = threadIdx.x, lane = tid & 31, w = tid >> 5;
    for (int i = tid; i < CIN * D2; i += 256) Wsm[i] = W[i];
    __syncthreads();
    float s = 0.f, ss = 0.f;
    for (int r = blockIdx.x * 8 + w; r < NPTS; r += G1GRID * 8) {
        float x0 = x[(size_t)r * CIN + lane];
        float x1 = x[(size_t)r * CIN + 32 + lane];
        float acc = 0.f;
        #pragma unroll
        for (int i = 0; i < 32; i++)
            acc = fmaf(__shfl_sync(0xffffffffu, x0, i), Wsm[i * D2 + lane], acc);
        #pragma unroll
        for (int i = 0; i < 32; i++)
            acc = fmaf(__shfl_sync(0xffffffffu, x1, i), Wsm[(i + 32) * D2 + lane], acc);
        g_y1[(size_t)r * D2 + lane] = acc;
        s += acc; ss += acc * acc;
    }
    sred[w][lane] = s; ssred[w][lane] = ss;
    __syncthreads();
    if (tid < D2) {
        float S = 0.f, SS = 0.f;
        #pragma unroll
        for (int j = 0; j < 8; j++) { S += sred[j][tid]; SS += ssred[j][tid]; }
        g_p1[blockIdx.x * 2 * D2 + tid] = S;
        g_p1[blockIdx.x * 2 * D2 + D2 + tid] = SS;
    }
}

// ------- finalize BN stats -> folded affine (a, c). grid = C, block = 256 ---
// Each block reduces one channel over all partial blocks with 256-way MLP.
__global__ void k_fin(int stage, const float* __restrict__ g, const float* __restrict__ b)
{
    const float* part; int nblk; int C; float invn; float* a; float* c;
    if (stage == 1)      { part = g_p1; nblk = G1GRID; C = D2;   invn = 1.f / NPTS; a = g_a1; c = g_c1; }
    else if (stage == 2) { part = g_p2; nblk = KPGRID; C = D2;   invn = 1.f / MQ;   a = g_a2; c = g_c2; }
    else                 { part = g_p3; nblk = G5GRID; C = COUT; invn = 1.f / MQ;   a = g_a3; c = g_c3; }
    int ch = blockIdx.x;
    if (ch >= C) return;
    int tid = threadIdx.x, lane = tid & 31, w = tid >> 5;
    __shared__ float rs[8], rss[8];
    float s = 0.f, ss = 0.f;
    for (int i = tid; i < nblk; i += 256) {
        s  += part[i * 2 * C + ch];
        ss += part[i * 2 * C + C + ch];
    }
    #pragma unroll
    for (int o = 16; o > 0; o >>= 1) {
        s  += __shfl_down_sync(0xffffffffu, s, o);
        ss += __shfl_down_sync(0xffffffffu, ss, o);
    }
    if (lane == 0) { rs[w] = s; rss[w] = ss; }
    __syncthreads();
    if (tid == 0) {
        float S = 0.f, SS = 0.f;
        #pragma unroll
        for (int j = 0; j < 8; j++) { S += rs[j]; SS += rss[j]; }
        float mu  = S * invn;
        float var = SS * invn - mu * mu;
        float A   = g[ch] * rsqrtf(var + EPS);
        a[ch] = A;
        c[ch] = b[ch] - mu * A;
    }
}

// ---------------- K3: KPConv (gather + weights, then A @ Kv) ----------------
// smem: A[QPB][480] | Kv[480][32] | kx,ky,kz,k2[15] | red[2][8][32]
__global__ void k_kpconv(const float* __restrict__ pos, const float* __restrict__ qpos,
                         const int* __restrict__ idx, const float* __restrict__ Kpts,
                         const float* __restrict__ Kv)
{
    extern __shared__ float smem[];
    float* A   = smem;                 // QPB*KD = 30720
    float* Kvs = A + QPB * KD;         // 15360
    float* kx  = Kvs + KD * D2;
    float* ky  = kx + KP;
    float* kz  = ky + KP;
    float* k2  = kz + KP;
    float* red = k2 + KP;              // 512

    int tid = threadIdx.x, lane = tid & 31, w = tid >> 5;
    for (int i = tid; i < KD * D2; i += 256) Kvs[i] = Kv[i];
    if (tid < KP) {
        float a = Kpts[tid * 3], b = Kpts[tid * 3 + 1], cc = Kpts[tid * 3 + 2];
        kx[tid] = a; ky[tid] = b; kz[tid] = cc; k2[tid] = a * a + b * b + cc * cc;
    }
    __syncthreads();

    float a1 = g_a1[lane], c1 = g_c1[lane];
    int q0 = blockIdx.x * QPB;

    // ---- phase 1: warp per query (8 queries per warp) ----
    for (int j = 0; j < 8; j++) {
        int m = q0 + w * 8 + j;
        float wacc[KP];
        #pragma unroll
        for (int k = 0; k < KP; k++) wacc[k] = 0.f;
        if (m < MQ) {
            float qx = __ldg(&qpos[m * 3]), qy = __ldg(&qpos[m * 3 + 1]), qz = __ldg(&qpos[m * 3 + 2]);
            int idv = (lane < NBR) ? __ldg(&idx[m * NBR + lane]) : NPTS;
            #pragma unroll
            for (int nb = 0; nb < NBR; nb++) {
                int id = __shfl_sync(0xffffffffu, idv, nb);
                if (id < NPTS) {
                    float rx = __ldg(&pos[id * 3])     - qx;
                    float ry = __ldg(&pos[id * 3 + 1]) - qy;
                    float rz = __ldg(&pos[id * 3 + 2]) - qz;
                    float r2 = rx * rx + ry * ry + rz * rz;
                    float wk = 0.f;
                    if (lane < KP) {
                        float sq = r2 + k2[lane]
                                 - 2.f * (rx * kx[lane] + ry * ky[lane] + rz * kz[lane]);
                        float d = sqrtf(fmaxf(sq, 0.f));
                        wk = fmaxf(1.f - d * INV_EXTENT, 0.f);
                    }
                    float f = __ldg(&g_y1[(size_t)id * D2 + lane]);
                    f = leaky(fmaf(a1, f, c1));
                    #pragma unroll
                    for (int k = 0; k < KP; k++)
                        wacc[k] = fmaf(__shfl_sync(0xffffffffu, wk, k), f, wacc[k]);
                }
            }
        }
        #pragma unroll
        for (int k = 0; k < KP; k++)
            A[(w * 8 + j) * KD + k * D2 + lane] = wacc[k];
    }
    __syncthreads();

    // ---- phase 2: out[q][e] = sum_kd A[q][kd] * Kv[kd][e], 8 queries/thread ----
    int e = lane, qs = w;
    float acc[8];
    #pragma unroll
    for (int j = 0; j < 8; j++) acc[j] = 0.f;
    const float* Arow = A + qs * 8 * KD;
    for (int kd = 0; kd < KD; kd += 4) {
        float kv0 = Kvs[(kd + 0) * D2 + e];
        float kv1 = Kvs[(kd + 1) * D2 + e];
        float kv2 = Kvs[(kd + 2) * D2 + e];
        float kv3 = Kvs[(kd + 3) * D2 + e];
        #pragma unroll
        for (int j = 0; j < 8; j++) {
            float4 av = *(const float4*)(Arow + j * KD + kd);
            acc[j] = fmaf(kv0, av.x, acc[j]);
            acc[j] = fmaf(kv1, av.y, acc[j]);
            acc[j] = fmaf(kv2, av.z, acc[j]);
            acc[j] = fmaf(kv3, av.w, acc[j]);
        }
    }
    float s = 0.f, ss = 0.f;
    #pragma unroll
    for (int j = 0; j < 8; j++) {
        int m = q0 + qs * 8 + j;
        if (m < MQ) {
            g_kp[(size_t)m * D2 + e] = acc[j];
            s += acc[j]; ss += acc[j] * acc[j];
        }
    }
    red[w * D2 + e] = s;
    red[256 + w * D2 + e] = ss;
    __syncthreads();
    if (tid < D2) {
        float S = 0.f, SS = 0.f;
        #pragma unroll
        for (int j = 0; j < 8; j++) { S += red[j * D2 + tid]; SS += red[256 + j * D2 + tid]; }
        g_p2[blockIdx.x * 2 * D2 + tid] = S;
        g_p2[blockIdx.x * 2 * D2 + D2 + tid] = SS;
    }
}

// ---------------- K5: h2 = act(bn2(kp)); y3 = h2 @ W_u2; stats3 -------------
__global__ void k_gemm2(const float* __restrict__ W2)
{
    __shared__ float Wsm[D2 * COUT];
    __shared__ float red[2][8][COUT];
    int tid = threadIdx.x, lane = tid & 31, w = tid >> 5;
    for (int i = tid; i < D2 * COUT; i += 256) Wsm[i] = W2[i];
    __syncthreads();
    float a2 = g_a2[lane], c2 = g_c2[lane];
    float s[4] = {0, 0, 0, 0}, ss[4] = {0, 0, 0, 0};
    for (int m = blockIdx.x * 8 + w; m < MQ; m += G5GRID * 8) {
        float v = g_kp[(size_t)m * D2 + lane];
        float h = leaky(fmaf(a2, v, c2));
        float a0 = 0.f, b0 = 0.f, cc0 = 0.f, d0 = 0.f;
        #pragma unroll
        for (int i = 0; i < 32; i++) {
            float hv = __shfl_sync(0xffffffffu, h, i);
            a0  = fmaf(hv, Wsm[i * COUT + lane],      a0);
            b0  = fmaf(hv, Wsm[i * COUT + 32 + lane], b0);
            cc0 = fmaf(hv, Wsm[i * COUT + 64 + lane], cc0);
            d0  = fmaf(hv, Wsm[i * COUT + 96 + lane], d0);
        }
        size_t o = (size_t)m * COUT;
        g_y3[o + lane] = a0; g_y3[o + 32 + lane] = b0;
        g_y3[o + 64 + lane] = cc0; g_y3[o + 96 + lane] = d0;
        s[0] += a0;  ss[0] += a0 * a0;   s[1] += b0;  ss[1] += b0 * b0;
        s[2] += cc0; ss[2] += cc0 * cc0; s[3] += d0;  ss[3] += d0 * d0;
    }
    #pragma unroll
    for (int r = 0; r < 4; r++) {
        red[0][w][lane + 32 * r] = s[r];
        red[1][w][lane + 32 * r] = ss[r];
    }
    __syncthreads();
    if (tid < COUT) {
        float S = 0.f, SS = 0.f;
        #pragma unroll
        for (int j = 0; j < 8; j++) { S += red[0][j][tid]; SS += red[1][j][tid]; }
        g_p3[blockIdx.x * 2 * COUT + tid] = S;
        g_p3[blockIdx.x * 2 * COUT + COUT + tid] = SS;
    }
}

// ---------------- K7: shortcut max-pool gather ------------------------------
__global__ void k_sx(const float* __restrict__ x, const int* __restrict__ idx)
{
    int tid = threadIdx.x, lane = tid & 31, w = tid >> 5;
    int m = blockIdx.x * 8 + w;
    if (m >= MQ) return;
    float m0 = -INFINITY, m1 = -INFINITY;
    int idv = (lane < NBR) ? __ldg(&idx[m * NBR + lane]) : NPTS;
    #pragma unroll
    for (int nb = 0; nb < NBR; nb++) {
        int id = __shfl_sync(0xffffffffu, idv, nb);
        float v0 = 0.f, v1 = 0.f;
        if (id < NPTS) {
            v0 = __ldg(&x[(size_t)id * CIN + lane]);
            v1 = __ldg(&x[(size_t)id * CIN + 32 + lane]);
        }
        m0 = fmaxf(m0, v0);
        m1 = fmaxf(m1, v1);
    }
    g_sx[(size_t)m * CIN + lane] = m0;
    g_sx[(size_t)m * CIN + 32 + lane] = m1;
}

// ---------------- K8: out = act(bn3(y3)) + sx @ W_sc ------------------------
__global__ void k_final(const float* __restrict__ Wsc, float* __restrict__ out)
{
    __shared__ float Wsm[CIN * COUT];   // 32 KB
    int tid = threadIdx.x, lane = tid & 31, w = tid >> 5;
    for (int i = tid; i < CIN * COUT; i += 256) Wsm[i] = Wsc[i];
    __syncthreads();
    int m = blockIdx.x * 8 + w;
    if (m >= MQ) return;
    float s0 = g_sx[(size_t)m * CIN + lane];
    float s1 = g_sx[(size_t)m * CIN + 32 + lane];
    float acc0 = 0.f, acc1 = 0.f, acc2 = 0.f, acc3 = 0.f;
    #pragma unroll
    for (int i = 0; i < 32; i++) {
        float sv = __shfl_sync(0xffffffffu, s0, i);
        acc0 = fmaf(sv, Wsm[i * COUT + lane],      acc0);
        acc1 = fmaf(sv, Wsm[i * COUT + 32 + lane], acc1);
        acc2 = fmaf(sv, Wsm[i * COUT + 64 + lane], acc2);
        acc3 = fmaf(sv, Wsm[i * COUT + 96 + lane], acc3);
    }
    #pragma unroll
    for (int i = 0; i < 32; i++) {
        float sv = __shfl_sync(0xffffffffu, s1, i);
        acc0 = fmaf(sv, Wsm[(i + 32) * COUT + lane],      acc0);
        acc1 = fmaf(sv, Wsm[(i + 32) * COUT + 32 + lane], acc1);
        acc2 = fmaf(sv, Wsm[(i + 32) * COUT + 64 + lane], acc2);
        acc3 = fmaf(sv, Wsm[(i + 32) * COUT + 96 + lane], acc3);
    }
    size_t o = (size_t)m * COUT;
    float accs[4] = {acc0, acc1, acc2, acc3};
    #pragma unroll
    for (int r = 0; r < 4; r++) {
        int e = lane + 32 * r;
        float y = g_y3[o + e];
        float h = leaky(fmaf(g_a3[e], y, g_c3[e]));
        out[o + e] = h + accs[r];
    }
}

// ---------------- launch ----------------------------------------------------
extern "C" void kernel_launch(void* const* d_in, const int* in_sizes, int n_in,
                              void* d_out, int out_size)
{
    const float* x    = (const float*)d_in[0];
    const float* pos  = (const float*)d_in[1];
    const float* qpos = (const float*)d_in[2];
    const int*   idx  = (const int*)d_in[3];
    const float* Wu1  = (const float*)d_in[4];
    const float* g1   = (const float*)d_in[5];
    const float* b1   = (const float*)d_in[6];
    const float* Kpts = (const float*)d_in[7];
    const float* Kv   = (const float*)d_in[8];
    const float* gk   = (const float*)d_in[9];
    const float* bk   = (const float*)d_in[10];
    const float* Wu2  = (const float*)d_in[11];
    const float* g2   = (const float*)d_in[12];
    const float* b2   = (const float*)d_in[13];
    const float* Wsc  = (const float*)d_in[14];
    float* out = (float*)d_out;

    const int SMEM_KP = (QPB * KD + KD * D2 + 4 * KP + 512) * (int)sizeof(float); // 186608
    cudaFuncSetAttribute(k_kpconv, cudaFuncAttributeMaxDynamicSharedMemorySize, SMEM_KP);

    k_gemm1<<<G1GRID, 256>>>(x, Wu1);
    k_fin<<<D2, 256>>>(1, g1, b1);
    k_kpconv<<<KPGRID, 256, SMEM_KP>>>(pos, qpos, idx, Kpts, Kv);
    k_fin<<<D2, 256>>>(2, gk, bk);
    k_gemm2<<<G5GRID, 256>>>(Wu2);
    k_fin<<<COUT, 256>>>(3, g2, b2);
    k_sx<<<(MQ + 7) / 8, 256>>>(x, idx);
    k_final<<<(MQ + 7) / 8, 256>>>(Wsc, out);
}